// round 1
// baseline (speedup 1.0000x reference)
#include <cuda_runtime.h>
#include <math.h>

#define H 32
#define F 8
#define TCH 128
#define NWARP 8
#define SEG (TCH / NWARP)   // 16
#define FULL 0xffffffffu

// Folded weights computed once per launch by setup_kernel.
__device__ float g_wX[4 * F * H];   // [m][f][k]: m=0 W_embed, m=1 We@Wd1, m=2 We@Wg1, m=3 We@Wd2
__device__ float g_bias[4 * H];     // m=0 b_embed, m=1 be@Wd1+bd1, m=2 be@Wg1+bg1, m=3 be@Wd2+bd2
__device__ float g_Aexp[2 * H];     // exp(A_log)

struct SmemLayout {
    float xs[TCH * F];
    float cA1[TCH * H];
    float cX1[TCH * H];
    float cE [TCH * H];
    float cG1[TCH * H];
    float cU2[TCH * H];
    float segA[NWARP * H];
    float segX[NWARP * H];
    float sstart[NWARP * H];
    float carry1[H];
    float s2c[H];
    float hlast[H];
    float swX[4 * F * H];
    float sbias[4 * H];
    float sA[2 * H];
    float sWd2[H * H];
    float sWg2[H * H];
    float sW1[H * H];
    float sbg2[H];
    float sb1[H];
    float sW2[H];
    float sgam[H];
    float sbet[H];
    float sb2;
};

__device__ __forceinline__ float softplus_f(float u) {
    return fmaxf(u, 0.f) + __logf(1.f + __expf(-fabsf(u)));
}
__device__ __forceinline__ float sigmoid_f(float u) {
    return __fdividef(1.f, 1.f + __expf(-u));
}
__device__ __forceinline__ float gelu_f(float u) {
    // tanh approximation (jax.nn.gelu approximate=True)
    float inner = 0.7978845608028654f * fmaf(0.044715f * u, u * u, u);
    float ex = __expf(2.f * inner);
    float th = 1.f - __fdividef(2.f, ex + 1.f);
    return 0.5f * u * (1.f + th);
}
__device__ __forceinline__ float warp_allsum(float v) {
    #pragma unroll
    for (int off = 16; off; off >>= 1) v += __shfl_xor_sync(FULL, v, off);
    return v;
}

__global__ void setup_kernel(const float* __restrict__ We, const float* __restrict__ be,
                             const float* __restrict__ Wd, const float* __restrict__ bd,
                             const float* __restrict__ Alog, const float* __restrict__ Wg,
                             const float* __restrict__ bg) {
    int tid = threadIdx.x;
    // m=0: W_embed copy
    for (int idx = tid; idx < F * H; idx += blockDim.x) g_wX[idx] = We[idx];
    // m=1..3: folded 8x32 = We @ M
    for (int idx = tid; idx < 3 * F * H; idx += blockDim.x) {
        int m = idx / (F * H);
        int r = idx % (F * H);
        int f = r / H, k = r % H;
        const float* M = (m == 0) ? Wd : (m == 1) ? Wg : (Wd + H * H);
        float s = 0.f;
        for (int h = 0; h < H; h++) s += We[f * H + h] * M[h * H + k];
        g_wX[(m + 1) * F * H + r] = s;
    }
    for (int idx = tid; idx < 4 * H; idx += blockDim.x) {
        int m = idx / H, k = idx % H;
        float v;
        if (m == 0) {
            v = be[k];
        } else {
            const float* M;
            const float* bb;
            if (m == 1)      { M = Wd;         bb = bd;     }
            else if (m == 2) { M = Wg;         bb = bg;     }
            else             { M = Wd + H * H; bb = bd + H; }
            float s = 0.f;
            for (int h = 0; h < H; h++) s += be[h] * M[h * H + k];
            v = s + bb[k];
        }
        g_bias[idx] = v;
    }
    for (int idx = tid; idx < 2 * H; idx += blockDim.x) g_Aexp[idx] = expf(Alog[idx]);
}

__global__ void __launch_bounds__(NWARP * 32, 2)
forecast_kernel(const float* __restrict__ x,
                const float* __restrict__ Wd, const float* __restrict__ bd,
                const float* __restrict__ Wg, const float* __restrict__ bg,
                const float* __restrict__ gamma_, const float* __restrict__ beta_,
                const float* __restrict__ W1, const float* __restrict__ b1,
                const float* __restrict__ W2, const float* __restrict__ b2,
                float* __restrict__ out, int S) {
    extern __shared__ float smraw[];
    SmemLayout& sm = *reinterpret_cast<SmemLayout*>(smraw);
    const int tid  = threadIdx.x;
    const int lane = tid & 31;
    const int w    = tid >> 5;
    const int b    = blockIdx.x;

    // ---- stage weights into smem ----
    for (int i = tid; i < 4 * F * H; i += blockDim.x) sm.swX[i] = g_wX[i];
    for (int i = tid; i < 4 * H; i += blockDim.x) sm.sbias[i] = g_bias[i];
    for (int i = tid; i < 2 * H; i += blockDim.x) sm.sA[i] = g_Aexp[i];
    for (int i = tid; i < H * H; i += blockDim.x) {
        sm.sWd2[i] = Wd[H * H + i];
        sm.sWg2[i] = Wg[H * H + i];
        sm.sW1[i]  = W1[i];
    }
    for (int i = tid; i < H; i += blockDim.x) {
        sm.sbg2[i] = bg[H + i];
        sm.sb1[i]  = b1[i];
        sm.sW2[i]  = W2[i];
        sm.sgam[i] = gamma_[i];
        sm.sbet[i] = beta_[i];
        sm.carry1[i] = 0.f;
        sm.s2c[i]    = 0.f;
    }
    if (tid == 0) sm.sb2 = b2[0];
    __syncthreads();

    // ---- per-lane register weights ----
    float wXr[4][F];
    #pragma unroll
    for (int m = 0; m < 4; m++)
        #pragma unroll
        for (int j = 0; j < F; j++) wXr[m][j] = sm.swX[m * F * H + j * H + lane];
    const float bR0 = sm.sbias[lane];
    const float bR1 = sm.sbias[H + lane];
    const float bR2 = sm.sbias[2 * H + lane];
    const float bR3 = sm.sbias[3 * H + lane];
    const float A1k = sm.sA[lane];
    const float A2k = sm.sA[H + lane];
    float wd2r[H];
    #pragma unroll
    for (int j = 0; j < H; j++) wd2r[j] = sm.sWd2[j * H + lane];

    const int nchunk = S / TCH;
    for (int c = 0; c < nchunk; c++) {
        const int tb = c * TCH;
        // ---- P0: stage x chunk (coalesced, 256 float4) ----
        {
            const float4* src = reinterpret_cast<const float4*>(x + ((long)b * S + tb) * F);
            float4* dst = reinterpret_cast<float4*>(sm.xs);
            dst[tid] = src[tid];
        }
        __syncthreads();
        // ---- P1: parallel coefficients + per-warp segment transform (block 1) ----
        {
            float Aw = 1.f, Xw = 0.f;
            for (int i = 0; i < SEG; i++) {
                int t = w * SEG + i;
                const float4* xr = reinterpret_cast<const float4*>(sm.xs + t * F);
                float4 xa = xr[0], xb4 = xr[1];
                float xv[8] = {xa.x, xa.y, xa.z, xa.w, xb4.x, xb4.y, xb4.z, xb4.w};
                float e = bR0, u1 = bR1, ug = bR2, u2 = bR3;
                #pragma unroll
                for (int j = 0; j < F; j++) {
                    e  = fmaf(xv[j], wXr[0][j], e);
                    u1 = fmaf(xv[j], wXr[1][j], u1);
                    ug = fmaf(xv[j], wXr[2][j], ug);
                    u2 = fmaf(xv[j], wXr[3][j], u2);
                }
                float d1  = softplus_f(u1);
                float g1  = sigmoid_f(ug);
                float a1  = __expf(-d1 * A1k);
                float xi1 = d1 * e;
                Xw = fmaf(a1, Xw, xi1);
                Aw *= a1;
                sm.cA1[t * H + lane] = a1;
                sm.cX1[t * H + lane] = xi1;
                sm.cE [t * H + lane] = e;
                sm.cG1[t * H + lane] = g1;
                sm.cU2[t * H + lane] = u2;
            }
            sm.segA[w * H + lane] = Aw;
            sm.segX[w * H + lane] = Xw;
        }
        __syncthreads();
        // ---- P2b: cross-warp compose of block-1 segments (warp 0) ----
        if (w == 0) {
            float s = sm.carry1[lane];
            #pragma unroll
            for (int ww = 0; ww < NWARP; ww++) {
                sm.sstart[ww * H + lane] = s;
                s = fmaf(sm.segA[ww * H + lane], s, sm.segX[ww * H + lane]);
            }
            sm.carry1[lane] = s;
        }
        __syncthreads();
        // ---- P3+P4 fused: apply block-1 scan, v@Wd2 dot via shfl, block-2 transform ----
        {
            float s1 = sm.sstart[w * H + lane];
            float A2 = 1.f, X2 = 0.f;
            for (int i = 0; i < SEG; i++) {
                int t = w * SEG + i;
                float a1 = sm.cA1[t * H + lane];
                float xi = sm.cX1[t * H + lane];
                float g1 = sm.cG1[t * H + lane];
                float e  = sm.cE [t * H + lane];
                float u2 = sm.cU2[t * H + lane];
                s1 = fmaf(a1, s1, xi);
                float v  = s1 * g1;
                float h1 = e + v;
                float d0 = 0.f, d1a = 0.f, d2a = 0.f, d3a = 0.f;
                #pragma unroll
                for (int j = 0; j < H; j += 4) {
                    d0  = fmaf(__shfl_sync(FULL, v, j + 0), wd2r[j + 0], d0);
                    d1a = fmaf(__shfl_sync(FULL, v, j + 1), wd2r[j + 1], d1a);
                    d2a = fmaf(__shfl_sync(FULL, v, j + 2), wd2r[j + 2], d2a);
                    d3a = fmaf(__shfl_sync(FULL, v, j + 3), wd2r[j + 3], d3a);
                }
                u2 += (d0 + d1a) + (d2a + d3a);
                float dd2 = softplus_f(u2);
                float a2  = __expf(-dd2 * A2k);
                float x2  = dd2 * h1;
                X2 = fmaf(a2, X2, x2);
                A2 *= a2;
                if (tb + t == S - 1) sm.hlast[lane] = h1;
            }
            sm.segA[w * H + lane] = A2;
            sm.segX[w * H + lane] = X2;
        }
        __syncthreads();
        // ---- P5: fold block-2 segment transforms into final-state carry (warp 0) ----
        if (w == 0) {
            float s2 = sm.s2c[lane];
            #pragma unroll
            for (int ww = 0; ww < NWARP; ww++)
                s2 = fmaf(sm.segA[ww * H + lane], s2, sm.segX[ww * H + lane]);
            sm.s2c[lane] = s2;
        }
        __syncthreads();
    }

    // ---- epilogue: gate2, residual, LayerNorm, GELU MLP, output ----
    if (w == 0) {
        float hl = sm.hlast[lane];
        float ug2 = sm.sbg2[lane];
        #pragma unroll
        for (int j = 0; j < H; j++)
            ug2 = fmaf(__shfl_sync(FULL, hl, j), sm.sWg2[j * H + lane], ug2);
        float g2 = sigmoid_f(ug2);
        float h2 = hl + sm.s2c[lane] * g2;
        float mu = warp_allsum(h2) * (1.f / H);
        float d  = h2 - mu;
        float var = warp_allsum(d * d) * (1.f / H);
        float hn = d * rsqrtf(var + 1e-5f) * sm.sgam[lane] + sm.sbet[lane];
        float z1 = sm.sb1[lane];
        #pragma unroll
        for (int j = 0; j < H; j++)
            z1 = fmaf(__shfl_sync(FULL, hn, j), sm.sW1[j * H + lane], z1);
        float z = gelu_f(z1);
        float o = warp_allsum(z * sm.sW2[lane]);
        if (lane == 0) out[b] = o + sm.sb2;
    }
}

extern "C" void kernel_launch(void* const* d_in, const int* in_sizes, int n_in,
                              void* d_out, int out_size) {
    const float* x    = (const float*)d_in[0];
    const float* We   = (const float*)d_in[1];
    const float* be   = (const float*)d_in[2];
    const float* Wd   = (const float*)d_in[3];
    const float* bd   = (const float*)d_in[4];
    const float* Alog = (const float*)d_in[5];
    const float* Wg   = (const float*)d_in[6];
    const float* bg   = (const float*)d_in[7];
    const float* gam  = (const float*)d_in[8];
    const float* bet  = (const float*)d_in[9];
    const float* W1   = (const float*)d_in[10];
    const float* b1   = (const float*)d_in[11];
    const float* W2   = (const float*)d_in[12];
    const float* b2   = (const float*)d_in[13];
    float* out = (float*)d_out;

    int B = out_size;                  // 256
    int S = in_sizes[0] / (B * F);     // 4096

    setup_kernel<<<1, 256>>>(We, be, Wd, bd, Alog, Wg, bg);

    size_t smem = sizeof(SmemLayout);
    cudaFuncSetAttribute(forecast_kernel, cudaFuncAttributeMaxDynamicSharedMemorySize, (int)smem);
    forecast_kernel<<<B, NWARP * 32, smem>>>(x, Wd, bd, Wg, bg, gam, bet,
                                             W1, b1, W2, b2, out, S);
}

// round 3
// speedup vs baseline: 1.1934x; 1.1934x over previous
#include <cuda_runtime.h>
#include <math.h>

#define H 32
#define F 8
#define TCH 128
#define NWARP 16
#define SEG (TCH / NWARP)   // 8
#define NTHR (NWARP * 32)   // 512
#define FULL 0xffffffffu

// Folded weights computed once per launch by setup_kernel.
__device__ float g_wX[4 * F * H];   // m=0 W_embed, m=1 We@Wd1, m=2 We@Wg1, m=3 We@Wd2
__device__ float g_bias[4 * H];
__device__ float g_A[2 * H];        // exp(A_log)

struct SmemLayout {
    float xs[TCH * F];          // staged x chunk
    float cV[TCH * H];          // v = s1*g1 rows (for the dot)
    float cEU[TCH * H * 2];     // packed (e, u2) per (t,k)
    float segA[NWARP * H];
    float segX[NWARP * H];
    float sstart[NWARP * H];
    float seg2A[NWARP * H];
    float seg2X[NWARP * H];
    float carry1[H];
    float s2c[H];
    float hlast[H];
    float swX[4 * F * H];
    float sbias[4 * H];
    float sA[2 * H];
    float sWd2[H * H];
    float sWg2[H * H];
    float sW1[H * H];
    float sbg2[H];
    float sb1[H];
    float sW2[H];
    float sgam[H];
    float sbet[H];
    float sb2;
};

__device__ __forceinline__ float ex2f(float x) { float r; asm("ex2.approx.f32 %0,%1;" : "=f"(r) : "f"(x)); return r; }
__device__ __forceinline__ float lg2f(float x) { float r; asm("lg2.approx.f32 %0,%1;" : "=f"(r) : "f"(x)); return r; }
__device__ __forceinline__ float tanh_f(float x) { float r; asm("tanh.approx.f32 %0,%1;" : "=f"(r) : "f"(x)); return r; }

// d = softplus(u), a = exp(-A*d), computed in log2 domain: 3 MUFU total.
__device__ __forceinline__ void splus_decay(float u, float A, float& d, float& a) {
    const float L2E = 1.4426950408889634f;
    const float LN2 = 0.6931471805599453f;
    float p = ex2f(-fabsf(u) * L2E);
    float q = lg2f(1.f + p);
    float r = fmaf(fmaxf(u, 0.f), L2E, q);  // log2(1+e^u)
    d = r * LN2;
    a = ex2f(-A * r);
}

__device__ __forceinline__ float sigmoid_f(float u) {
    return fmaf(tanh_f(0.5f * u), 0.5f, 0.5f);
}

__device__ __forceinline__ float gelu_f(float u) {
    float inner = 0.7978845608028654f * fmaf(0.044715f * u, u * u, u);
    float ex = ex2f(2.f * inner * 1.4426950408889634f);
    float th = 1.f - __fdividef(2.f, ex + 1.f);
    return 0.5f * u * (1.f + th);
}

__device__ __forceinline__ float warp_allsum(float v) {
    #pragma unroll
    for (int off = 16; off; off >>= 1) v += __shfl_xor_sync(FULL, v, off);
    return v;
}

__global__ void setup_kernel(const float* __restrict__ We, const float* __restrict__ be,
                             const float* __restrict__ Wd, const float* __restrict__ bd,
                             const float* __restrict__ Alog, const float* __restrict__ Wg,
                             const float* __restrict__ bg) {
    int tid = threadIdx.x;
    for (int idx = tid; idx < F * H; idx += blockDim.x) g_wX[idx] = We[idx];
    for (int idx = tid; idx < 3 * F * H; idx += blockDim.x) {
        int m = idx / (F * H);
        int r = idx % (F * H);
        int f = r / H, k = r % H;
        const float* M = (m == 0) ? Wd : (m == 1) ? Wg : (Wd + H * H);
        float s = 0.f;
        for (int h = 0; h < H; h++) s += We[f * H + h] * M[h * H + k];
        g_wX[(m + 1) * F * H + r] = s;
    }
    for (int idx = tid; idx < 4 * H; idx += blockDim.x) {
        int m = idx / H, k = idx % H;
        float v;
        if (m == 0) v = be[k];
        else {
            const float* M; const float* bb;
            if (m == 1)      { M = Wd;         bb = bd;     }
            else if (m == 2) { M = Wg;         bb = bg;     }
            else             { M = Wd + H * H; bb = bd + H; }
            float s = 0.f;
            for (int h = 0; h < H; h++) s += be[h] * M[h * H + k];
            v = s + bb[k];
        }
        g_bias[idx] = v;
    }
    for (int idx = tid; idx < 2 * H; idx += blockDim.x) g_A[idx] = expf(Alog[idx]);
}

__global__ void __launch_bounds__(NTHR, 1)
forecast_kernel(const float* __restrict__ x,
                const float* __restrict__ Wd,
                const float* __restrict__ Wg, const float* __restrict__ bg,
                const float* __restrict__ gamma_, const float* __restrict__ beta_,
                const float* __restrict__ W1, const float* __restrict__ b1,
                const float* __restrict__ W2, const float* __restrict__ b2,
                float* __restrict__ out, int S) {
    extern __shared__ float smraw[];
    SmemLayout& sm = *reinterpret_cast<SmemLayout*>(smraw);
    const int tid  = threadIdx.x;
    const int lane = tid & 31;
    const int w    = tid >> 5;

    // ---- stage weights into smem (strided loops: no size/blockDim traps) ----
    for (int i = tid; i < 4 * F * H; i += NTHR) sm.swX[i] = g_wX[i];
    for (int i = tid; i < 4 * H; i += NTHR) sm.sbias[i] = g_bias[i];
    for (int i = tid; i < 2 * H; i += NTHR) sm.sA[i] = g_A[i];
    for (int i = tid; i < H * H; i += NTHR) {
        sm.sWd2[i] = Wd[H * H + i];
        sm.sWg2[i] = Wg[H * H + i];
        sm.sW1[i]  = W1[i];
    }
    for (int i = tid; i < H; i += NTHR) {
        sm.sbg2[i] = bg[H + i];
        sm.sb1[i]  = b1[i];
        sm.sW2[i]  = W2[i];
        sm.sgam[i] = gamma_[i];
        sm.sbet[i] = beta_[i];
    }
    if (tid == 0) sm.sb2 = b2[0];
    __syncthreads();

    // ---- per-lane register weights ----
    float wXr[4][F];
    #pragma unroll
    for (int m = 0; m < 4; m++)
        #pragma unroll
        for (int j = 0; j < F; j++) wXr[m][j] = sm.swX[m * F * H + j * H + lane];
    const float bR0 = sm.sbias[lane];
    const float bR1 = sm.sbias[H + lane];
    const float bR2 = sm.sbias[2 * H + lane];
    const float bR3 = sm.sbias[3 * H + lane];
    const float A1k = sm.sA[lane];
    const float A2k = sm.sA[H + lane];
    float wd2r[H];
    #pragma unroll
    for (int j = 0; j < H; j++) wd2r[j] = sm.sWd2[j * H + lane];

    const int nchunk = S / TCH;

    for (int bi = 0; bi < 2; bi++) {
        const int b = blockIdx.x * 2 + bi;

        // per-batch init
        if (tid < H) { sm.carry1[tid] = 0.f; sm.s2c[tid] = 0.f; }
        sm.seg2A[tid] = 1.f;
        sm.seg2X[tid] = 0.f;
        __syncthreads();

        for (int c = 0; c < nchunk; c++) {
            const int tb = c * TCH;
            // ---- P0: stage x chunk (256 float4, coalesced) ----
            if (tid < TCH * F / 4) {
                const float4* src = reinterpret_cast<const float4*>(x + ((long)b * S + tb) * F);
                reinterpret_cast<float4*>(sm.xs)[tid] = src[tid];
            }
            __syncthreads();

            // ---- P1: coefficients (registers) + block-1 segment transform ----
            float a1r[SEG], x1r[SEG], g1r[SEG];
            {
                float Aw = 1.f, Xw = 0.f;
                #pragma unroll
                for (int i = 0; i < SEG; i++) {
                    const int t = w * SEG + i;
                    const float4* xr = reinterpret_cast<const float4*>(sm.xs + t * F);
                    float4 xa = xr[0], xb4 = xr[1];
                    float xv[8] = {xa.x, xa.y, xa.z, xa.w, xb4.x, xb4.y, xb4.z, xb4.w};
                    float e = bR0, u1 = bR1, ug = bR2, u2 = bR3;
                    #pragma unroll
                    for (int j = 0; j < F; j++) {
                        e  = fmaf(xv[j], wXr[0][j], e);
                        u1 = fmaf(xv[j], wXr[1][j], u1);
                        ug = fmaf(xv[j], wXr[2][j], ug);
                        u2 = fmaf(xv[j], wXr[3][j], u2);
                    }
                    float d1, a1;
                    splus_decay(u1, A1k, d1, a1);
                    float g1  = sigmoid_f(ug);
                    float xi1 = d1 * e;
                    Xw = fmaf(a1, Xw, xi1);
                    Aw *= a1;
                    a1r[i] = a1; x1r[i] = xi1; g1r[i] = g1;
                    reinterpret_cast<float2*>(sm.cEU)[t * H + lane] = make_float2(e, u2);
                }
                sm.segA[w * H + lane] = Aw;
                sm.segX[w * H + lane] = Xw;
            }
            __syncthreads();

            // ---- P2b: warp 0 folds previous chunk's block-2 segs, composes block-1 ----
            if (w == 0) {
                float s2 = sm.s2c[lane];
                #pragma unroll
                for (int ww = 0; ww < NWARP; ww++)
                    s2 = fmaf(sm.seg2A[ww * H + lane], s2, sm.seg2X[ww * H + lane]);
                sm.s2c[lane] = s2;

                float s = sm.carry1[lane];
                #pragma unroll
                for (int ww = 0; ww < NWARP; ww++) {
                    sm.sstart[ww * H + lane] = s;
                    s = fmaf(sm.segA[ww * H + lane], s, sm.segX[ww * H + lane]);
                }
                sm.carry1[lane] = s;
            }
            __syncthreads();

            // ---- P3a: apply block-1 scan; stash v rows ----
            float h1r[SEG];
            {
                float s1 = sm.sstart[w * H + lane];
                #pragma unroll
                for (int i = 0; i < SEG; i++) {
                    const int t = w * SEG + i;
                    s1 = fmaf(a1r[i], s1, x1r[i]);
                    float v = s1 * g1r[i];
                    float e = sm.cEU[(t * H + lane) * 2];
                    h1r[i] = e + v;
                    sm.cV[t * H + lane] = v;
                    if (tb + t == S - 1) sm.hlast[lane] = h1r[i];
                }
            }
            __syncwarp();

            // ---- P3b+P4: dot v@Wd2 via broadcast LDS.128, block-2 transform ----
            {
                float A2 = 1.f, X2 = 0.f;
                #pragma unroll
                for (int i = 0; i < SEG; i++) {
                    const int t = w * SEG + i;
                    const float4* vr = reinterpret_cast<const float4*>(sm.cV + t * H);
                    float acc0 = 0.f, acc1 = 0.f, acc2 = 0.f, acc3 = 0.f;
                    #pragma unroll
                    for (int q = 0; q < 8; q++) {
                        float4 v4 = vr[q];
                        acc0 = fmaf(v4.x, wd2r[4 * q + 0], acc0);
                        acc1 = fmaf(v4.y, wd2r[4 * q + 1], acc1);
                        acc2 = fmaf(v4.z, wd2r[4 * q + 2], acc2);
                        acc3 = fmaf(v4.w, wd2r[4 * q + 3], acc3);
                    }
                    float u2 = sm.cEU[(t * H + lane) * 2 + 1] + ((acc0 + acc1) + (acc2 + acc3));
                    float d2, a2;
                    splus_decay(u2, A2k, d2, a2);
                    X2 = fmaf(a2, X2, d2 * h1r[i]);
                    A2 *= a2;
                }
                sm.seg2A[w * H + lane] = A2;
                sm.seg2X[w * H + lane] = X2;
            }
            __syncthreads();
        }

        // ---- final block-2 fold + epilogue (warp 0) ----
        if (w == 0) {
            float s2 = sm.s2c[lane];
            #pragma unroll
            for (int ww = 0; ww < NWARP; ww++)
                s2 = fmaf(sm.seg2A[ww * H + lane], s2, sm.seg2X[ww * H + lane]);

            float hl = sm.hlast[lane];
            float ug2 = sm.sbg2[lane];
            #pragma unroll
            for (int j = 0; j < H; j++)
                ug2 = fmaf(__shfl_sync(FULL, hl, j), sm.sWg2[j * H + lane], ug2);
            float g2 = sigmoid_f(ug2);
            float h2 = hl + s2 * g2;
            float mu = warp_allsum(h2) * (1.f / H);
            float d  = h2 - mu;
            float var = warp_allsum(d * d) * (1.f / H);
            float hn = d * rsqrtf(var + 1e-5f) * sm.sgam[lane] + sm.sbet[lane];
            float z1 = sm.sb1[lane];
            #pragma unroll
            for (int j = 0; j < H; j++)
                z1 = fmaf(__shfl_sync(FULL, hn, j), sm.sW1[j * H + lane], z1);
            float z = gelu_f(z1);
            float o = warp_allsum(z * sm.sW2[lane]);
            if (lane == 0) out[b] = o + sm.sb2;
        }
        __syncthreads();
    }
}

extern "C" void kernel_launch(void* const* d_in, const int* in_sizes, int n_in,
                              void* d_out, int out_size) {
    const float* x    = (const float*)d_in[0];
    const float* We   = (const float*)d_in[1];
    const float* be   = (const float*)d_in[2];
    const float* Wd   = (const float*)d_in[3];
    const float* bd   = (const float*)d_in[4];
    const float* Alog = (const float*)d_in[5];
    const float* Wg   = (const float*)d_in[6];
    const float* bg   = (const float*)d_in[7];
    const float* gam  = (const float*)d_in[8];
    const float* bet  = (const float*)d_in[9];
    const float* W1   = (const float*)d_in[10];
    const float* b1   = (const float*)d_in[11];
    const float* W2   = (const float*)d_in[12];
    const float* b2   = (const float*)d_in[13];
    float* out = (float*)d_out;

    int B = out_size;                  // 256
    int S = in_sizes[0] / (B * F);     // 4096

    setup_kernel<<<1, 256>>>(We, be, Wd, bd, Alog, Wg, bg);

    size_t smem = sizeof(SmemLayout);
    cudaFuncSetAttribute(forecast_kernel, cudaFuncAttributeMaxDynamicSharedMemorySize, (int)smem);
    forecast_kernel<<<B / 2, NTHR, smem>>>(x, Wd, Wg, bg, gam, bet,
                                           W1, b1, W2, b2, out, S);
}

// round 4
// speedup vs baseline: 1.2843x; 1.0762x over previous
#include <cuda_runtime.h>
#include <math.h>

#define H 32
#define F 8
#define TCH 64
#define NWARP 8
#define SEG (TCH / NWARP)   // 8
#define NTHR (NWARP * 32)   // 256
#define FULL 0xffffffffu

typedef unsigned long long ull;

// Folded weights computed once per launch by setup_kernel.
__device__ float g_wX[4 * F * H];   // m=0 W_embed, m=1 We@Wd1, m=2 We@Wg1, m=3 We@Wd2
__device__ float g_bias[4 * H];
__device__ float g_A[2 * H];        // exp(A_log)

struct SmemLayout {
    float4 xs[2][TCH * F / 4];   // double-buffered x chunk
    float  cV[TCH * H];          // v rows (16B-aligned rows for longlong2 loads)
    float2 cEU[TCH * H];         // packed (e, u2)
    float2 segAX[NWARP * H];     // block-1 segment transforms (this chunk)
    float2 seg2[2][NWARP * H];   // block-2 segment transforms (double-buffered)
    float  hlast[H];
    float  swX[4 * F * H];
    float  sbias[4 * H];
    float  sA[2 * H];
    float  sWd2[H * H];
    float  sWg2[H * H];
    float  sW1[H * H];
    float  sbg2[H];
    float  sb1[H];
    float  sW2[H];
    float  sgam[H];
    float  sbet[H];
    float  sb2;
};

__device__ __forceinline__ float ex2f(float x) { float r; asm("ex2.approx.f32 %0,%1;" : "=f"(r) : "f"(x)); return r; }
__device__ __forceinline__ float lg2f(float x) { float r; asm("lg2.approx.f32 %0,%1;" : "=f"(r) : "f"(x)); return r; }
__device__ __forceinline__ float tanh_f(float x) { float r; asm("tanh.approx.f32 %0,%1;" : "=f"(r) : "f"(x)); return r; }

__device__ __forceinline__ ull pack2(float lo, float hi) {
    ull r; asm("mov.b64 %0, {%1, %2};" : "=l"(r) : "r"(__float_as_uint(lo)), "r"(__float_as_uint(hi)));
    return r;
}
__device__ __forceinline__ ull splat2(float x) {
    ull r; asm("mov.b64 %0, {%1, %1};" : "=l"(r) : "r"(__float_as_uint(x)));
    return r;
}
__device__ __forceinline__ float2 unpack2(ull v) {
    unsigned lo, hi; asm("mov.b64 {%0, %1}, %2;" : "=r"(lo), "=r"(hi) : "l"(v));
    return make_float2(__uint_as_float(lo), __uint_as_float(hi));
}
__device__ __forceinline__ void fma2(ull& d, ull a, ull b) {
    asm("fma.rn.f32x2 %0, %1, %2, %0;" : "+l"(d) : "l"(a), "l"(b));
}

// d = softplus(u), a = exp(-A*d), computed in log2 domain: 3 MUFU total.
__device__ __forceinline__ void splus_decay(float u, float A, float& d, float& a) {
    const float L2E = 1.4426950408889634f;
    const float LN2 = 0.6931471805599453f;
    float p = ex2f(-fabsf(u) * L2E);
    float q = lg2f(1.f + p);
    float r = fmaf(fmaxf(u, 0.f), L2E, q);  // log2(1+e^u)
    d = r * LN2;
    a = ex2f(-A * r);
}

__device__ __forceinline__ float sigmoid_f(float u) {
    return fmaf(tanh_f(0.5f * u), 0.5f, 0.5f);
}

__device__ __forceinline__ float gelu_f(float u) {
    float inner = 0.7978845608028654f * fmaf(0.044715f * u, u * u, u);
    float ex = ex2f(2.f * inner * 1.4426950408889634f);
    float th = 1.f - __fdividef(2.f, ex + 1.f);
    return 0.5f * u * (1.f + th);
}

__device__ __forceinline__ float warp_allsum(float v) {
    #pragma unroll
    for (int off = 16; off; off >>= 1) v += __shfl_xor_sync(FULL, v, off);
    return v;
}

__global__ void setup_kernel(const float* __restrict__ We, const float* __restrict__ be,
                             const float* __restrict__ Wd, const float* __restrict__ bd,
                             const float* __restrict__ Alog, const float* __restrict__ Wg,
                             const float* __restrict__ bg) {
    int tid = threadIdx.x;
    for (int idx = tid; idx < F * H; idx += blockDim.x) g_wX[idx] = We[idx];
    for (int idx = tid; idx < 3 * F * H; idx += blockDim.x) {
        int m = idx / (F * H);
        int r = idx % (F * H);
        int f = r / H, k = r % H;
        const float* M = (m == 0) ? Wd : (m == 1) ? Wg : (Wd + H * H);
        float s = 0.f;
        for (int h = 0; h < H; h++) s += We[f * H + h] * M[h * H + k];
        g_wX[(m + 1) * F * H + r] = s;
    }
    for (int idx = tid; idx < 4 * H; idx += blockDim.x) {
        int m = idx / H, k = idx % H;
        float v;
        if (m == 0) v = be[k];
        else {
            const float* M; const float* bb;
            if (m == 1)      { M = Wd;         bb = bd;     }
            else if (m == 2) { M = Wg;         bb = bg;     }
            else             { M = Wd + H * H; bb = bd + H; }
            float s = 0.f;
            for (int h = 0; h < H; h++) s += be[h] * M[h * H + k];
            v = s + bb[k];
        }
        g_bias[idx] = v;
    }
    for (int idx = tid; idx < 2 * H; idx += blockDim.x) g_A[idx] = expf(Alog[idx]);
}

__global__ void __launch_bounds__(NTHR, 2)
forecast_kernel(const float* __restrict__ x,
                const float* __restrict__ Wd,
                const float* __restrict__ Wg, const float* __restrict__ bg,
                const float* __restrict__ gamma_, const float* __restrict__ beta_,
                const float* __restrict__ W1, const float* __restrict__ b1,
                const float* __restrict__ W2, const float* __restrict__ b2,
                float* __restrict__ out, int S) {
    extern __shared__ float smraw[];
    SmemLayout& sm = *reinterpret_cast<SmemLayout*>(smraw);
    const int tid  = threadIdx.x;
    const int lane = tid & 31;
    const int w    = tid >> 5;
    const int b    = blockIdx.x;
    const int nchunk = S / TCH;

    // ---- stage weights into smem ----
    for (int i = tid; i < 4 * F * H; i += NTHR) sm.swX[i] = g_wX[i];
    for (int i = tid; i < 4 * H; i += NTHR) sm.sbias[i] = g_bias[i];
    for (int i = tid; i < 2 * H; i += NTHR) sm.sA[i] = g_A[i];
    for (int i = tid; i < H * H; i += NTHR) {
        sm.sWd2[i] = Wd[H * H + i];
        sm.sWg2[i] = Wg[H * H + i];
        sm.sW1[i]  = W1[i];
    }
    for (int i = tid; i < H; i += NTHR) {
        sm.sbg2[i] = bg[H + i];
        sm.sb1[i]  = b1[i];
        sm.sW2[i]  = W2[i];
        sm.sgam[i] = gamma_[i];
        sm.sbet[i] = beta_[i];
    }
    if (tid == 0) sm.sb2 = b2[0];
    // seg2 read-buffer for chunk 0 = identity
    sm.seg2[1][tid] = make_float2(1.f, 0.f);
    // stage xs[0]
    {
        const float4* src = reinterpret_cast<const float4*>(x + (long)b * S * F);
        if (tid < TCH * F / 4) sm.xs[0][tid] = src[tid];
    }
    __syncthreads();

    // ---- per-lane register weights (packed for f32x2) ----
    ull wp01[F], wp23[F];
    #pragma unroll
    for (int j = 0; j < F; j++) {
        wp01[j] = pack2(sm.swX[0 * F * H + j * H + lane], sm.swX[1 * F * H + j * H + lane]);
        wp23[j] = pack2(sm.swX[2 * F * H + j * H + lane], sm.swX[3 * F * H + j * H + lane]);
    }
    const ull bias01 = pack2(sm.sbias[lane],         sm.sbias[H + lane]);
    const ull bias23 = pack2(sm.sbias[2 * H + lane], sm.sbias[3 * H + lane]);
    const float A1k = sm.sA[lane];
    const float A2k = sm.sA[H + lane];
    ull wd2p[H / 2];
    #pragma unroll
    for (int p = 0; p < H / 2; p++)
        wd2p[p] = pack2(sm.sWd2[(2 * p) * H + lane], sm.sWd2[(2 * p + 1) * H + lane]);

    float carry1 = 0.f;   // replicated across warps
    float s2     = 0.f;   // replicated across warps (block-2 final-state carry)

    for (int c = 0; c < nchunk; c++) {
        const int cb = c & 1;
        // ================= PHASE A: coefficients + block-1 segment transform ====
        float a1r[SEG], x1r[SEG], g1r[SEG];
        {
            float Aw = 1.f, Xw = 0.f;
            #pragma unroll
            for (int i = 0; i < SEG; i++) {
                const int t = w * SEG + i;
                float4 xa = sm.xs[cb][t * 2];
                float4 xb4 = sm.xs[cb][t * 2 + 1];
                float xv[8] = {xa.x, xa.y, xa.z, xa.w, xb4.x, xb4.y, xb4.z, xb4.w};
                ull a01 = bias01, a23 = bias23;
                #pragma unroll
                for (int j = 0; j < F; j++) {
                    ull sp = splat2(xv[j]);
                    fma2(a01, sp, wp01[j]);
                    fma2(a23, sp, wp23[j]);
                }
                float2 eu1 = unpack2(a01);   // {e, u1}
                float2 gu2 = unpack2(a23);   // {ug, u2}
                float d1, a1;
                splus_decay(eu1.y, A1k, d1, a1);
                float g1  = sigmoid_f(gu2.x);
                float xi1 = d1 * eu1.x;
                Xw = fmaf(a1, Xw, xi1);
                Aw *= a1;
                a1r[i] = a1; x1r[i] = xi1; g1r[i] = g1;
                sm.cEU[t * H + lane] = make_float2(eu1.x, gu2.y);
            }
            sm.segAX[w * H + lane] = make_float2(Aw, Xw);
        }
        __syncthreads();

        // ================= PHASE B ==========================================
        // prefetch next x chunk
        if (c + 1 < nchunk && tid < TCH * F / 4) {
            const float4* src = reinterpret_cast<const float4*>(x + ((long)b * S + (c + 1) * TCH) * F);
            sm.xs[cb ^ 1][tid] = src[tid];
        }
        // redundant fold (all warps): block-1 prefix start + new carry
        float st = 0.f;
        {
            float s = carry1;
            #pragma unroll
            for (int ww = 0; ww < NWARP; ww++) {
                float2 ax = sm.segAX[ww * H + lane];
                if (ww == w) st = s;
                s = fmaf(ax.x, s, ax.y);
            }
            carry1 = s;
        }
        // redundant fold: block-2 partials of previous chunk
        {
            const float2* rd = sm.seg2[cb ^ 1];
            #pragma unroll
            for (int ww = 0; ww < NWARP; ww++) {
                float2 ax = rd[ww * H + lane];
                s2 = fmaf(ax.x, s2, ax.y);
            }
        }
        // P3a: apply block-1 scan, stash v rows
        float h1r[SEG];
        {
            float s1 = st;
            #pragma unroll
            for (int i = 0; i < SEG; i++) {
                const int t = w * SEG + i;
                s1 = fmaf(a1r[i], s1, x1r[i]);
                float v = s1 * g1r[i];
                h1r[i] = sm.cEU[t * H + lane].x + v;
                sm.cV[t * H + lane] = v;
            }
            if (c == nchunk - 1 && w == NWARP - 1) sm.hlast[lane] = h1r[SEG - 1];
        }
        __syncwarp();
        // P3b: dot v@Wd2 via paired LDS.128 + fma.f32x2, block-2 transform
        {
            float A2 = 1.f, X2 = 0.f;
            #pragma unroll
            for (int i = 0; i < SEG; i++) {
                const int t = w * SEG + i;
                const longlong2* vr = reinterpret_cast<const longlong2*>(sm.cV + t * H);
                ull accA = 0ull, accB = 0ull;
                #pragma unroll
                for (int q = 0; q < 8; q++) {
                    longlong2 vq = vr[q];
                    fma2(accA, (ull)vq.x, wd2p[2 * q]);
                    fma2(accB, (ull)vq.y, wd2p[2 * q + 1]);
                }
                float2 fa = unpack2(accA), fb = unpack2(accB);
                float u2 = sm.cEU[t * H + lane].y + ((fa.x + fa.y) + (fb.x + fb.y));
                float d2, a2;
                splus_decay(u2, A2k, d2, a2);
                X2 = fmaf(a2, X2, d2 * h1r[i]);
                A2 *= a2;
            }
            sm.seg2[cb][w * H + lane] = make_float2(A2, X2);
        }
        __syncthreads();
    }

    // ---- epilogue (warp 0): fold last chunk's block-2 partials, gate2, LN, MLP ----
    if (w == 0) {
        const float2* fin = sm.seg2[(nchunk - 1) & 1];
        #pragma unroll
        for (int ww = 0; ww < NWARP; ww++) {
            float2 ax = fin[ww * H + lane];
            s2 = fmaf(ax.x, s2, ax.y);
        }
        float hl = sm.hlast[lane];
        float ug2 = sm.sbg2[lane];
        #pragma unroll
        for (int j = 0; j < H; j++)
            ug2 = fmaf(__shfl_sync(FULL, hl, j), sm.sWg2[j * H + lane], ug2);
        float g2 = sigmoid_f(ug2);
        float h2 = hl + s2 * g2;
        float mu = warp_allsum(h2) * (1.f / H);
        float d  = h2 - mu;
        float var = warp_allsum(d * d) * (1.f / H);
        float hn = d * rsqrtf(var + 1e-5f) * sm.sgam[lane] + sm.sbet[lane];
        float z1 = sm.sb1[lane];
        #pragma unroll
        for (int j = 0; j < H; j++)
            z1 = fmaf(__shfl_sync(FULL, hn, j), sm.sW1[j * H + lane], z1);
        float z = gelu_f(z1);
        float o = warp_allsum(z * sm.sW2[lane]);
        if (lane == 0) out[b] = o + sm.sb2;
    }
}

extern "C" void kernel_launch(void* const* d_in, const int* in_sizes, int n_in,
                              void* d_out, int out_size) {
    const float* x    = (const float*)d_in[0];
    const float* We   = (const float*)d_in[1];
    const float* be   = (const float*)d_in[2];
    const float* Wd   = (const float*)d_in[3];
    const float* bd   = (const float*)d_in[4];
    const float* Alog = (const float*)d_in[5];
    const float* Wg   = (const float*)d_in[6];
    const float* bg   = (const float*)d_in[7];
    const float* gam  = (const float*)d_in[8];
    const float* bet  = (const float*)d_in[9];
    const float* W1   = (const float*)d_in[10];
    const float* b1   = (const float*)d_in[11];
    const float* W2   = (const float*)d_in[12];
    const float* b2   = (const float*)d_in[13];
    float* out = (float*)d_out;

    int B = out_size;                  // 256
    int S = in_sizes[0] / (B * F);     // 4096

    setup_kernel<<<1, 256>>>(We, be, Wd, bd, Alog, Wg, bg);

    size_t smem = sizeof(SmemLayout);
    cudaFuncSetAttribute(forecast_kernel, cudaFuncAttributeMaxDynamicSharedMemorySize, (int)smem);
    forecast_kernel<<<B, NTHR, smem>>>(x, Wd, Wg, bg, gam, bet,
                                       W1, b1, W2, b2, out, S);
}